// round 1
// baseline (speedup 1.0000x reference)
#include <cuda_runtime.h>
#include <cstdint>

#define B_SZ            16384
#define D_DIM           32
#define H_DIM           64
#define T_STEPS         50
#define NSUB            2

#define ELEMS_PER_CTA   16
#define THREADS_PER_CTA 64      // 4 threads cooperate per batch element
#define XSTRIDE         34      // padded x stride (floats) -> conflict-free LDS.64
#define WROWSTR         160     // per-c row stride (floats) in remapped weight layout
#define WSUBSTR         40      // per-s sub-stride (floats): banks shift by 8 per s

// ---------------- f32x2 packed helpers (Blackwell FFMA2 path) ----------------
__device__ __forceinline__ uint64_t pack2(float lo, float hi) {
    uint64_t r; asm("mov.b64 %0, {%1, %2};" : "=l"(r) : "f"(lo), "f"(hi)); return r;
}
__device__ __forceinline__ void unpack2(uint64_t v, float& lo, float& hi) {
    asm("mov.b64 {%0, %1}, %2;" : "=f"(lo), "=f"(hi) : "l"(v));
}
__device__ __forceinline__ uint64_t fma2(uint64_t a, uint64_t b, uint64_t c) {
    uint64_t d; asm("fma.rn.f32x2 %0, %1, %2, %3;" : "=l"(d) : "l"(a), "l"(b), "l"(c)); return d;
}
__device__ __forceinline__ uint64_t add2(uint64_t a, uint64_t b) {
    uint64_t d; asm("add.rn.f32x2 %0, %1, %2;" : "=l"(d) : "l"(a), "l"(b)); return d;
}
// tanh(x) = 1 - 2/(exp(2x)+1) via MUFU EX2/RCP. Rel err ~1e-6 (safe for 1e-3 after
// RK4 error amplification; tanh.approx's ~6e-4 would not be).
__device__ __forceinline__ float fast_tanh(float x) {
    float e; asm("ex2.approx.f32 %0, %1;" : "=f"(e) : "f"(x * 2.885390082f)); // 2*log2(e)
    float r; asm("rcp.approx.f32 %0, %1;" : "=f"(r) : "f"(e + 1.0f));
    return fmaf(-2.0f, r, 1.0f);   // graceful at +-inf -> +-1
}

struct SmemLayout {
    float w1[2560];   // W1^T remapped: [(j&15)*160 + (j>>4)*40 + i] = W1[i][j]
    float w2[2560];   // W2   remapped: [(j&15)*160 + (j>>4)*40 + i] = W2[j][i]
    float b1g[64];    // b1 remapped:   [(j&15)*4 + (j>>4)]
    float b2[32];
    float x[ELEMS_PER_CTA * XSTRIDE];
    float times[T_STEPS];
};

// Vector field eval for this thread's 16 hidden units; yp returns the FULL
// reduced output (butterfly over the 4-lane quad) plus b2.
__device__ __forceinline__ void eval_field(
    const uint64_t* __restrict__ zp, uint64_t* __restrict__ yp,
    const float* __restrict__ w1b, const float* __restrict__ w2b,
    const float* __restrict__ b1b, const float* __restrict__ sB2)
{
#pragma unroll
    for (int p = 0; p < 16; p++) yp[p] = 0ull;

    const float* p1 = w1b;
    const float* p2 = w2b;
#pragma unroll 1
    for (int g = 0; g < 4; g++) {               // 4 groups of 4 hidden units (ILP=4)
        uint64_t h[4], th[4];
#pragma unroll
        for (int q = 0; q < 4; q++) h[q] = pack2(b1b[(g * 4 + q) * 4], 0.0f);
        // layer 1: h_j = b1_j + sum_i z_i * W1[i][j]
#pragma unroll
        for (int i = 0; i < 32; i += 4) {
#pragma unroll
            for (int q = 0; q < 4; q++) {
                const ulonglong2 w = *reinterpret_cast<const ulonglong2*>(p1 + q * WROWSTR + i);
                h[q] = fma2(zp[i >> 1],       w.x, h[q]);
                h[q] = fma2(zp[(i >> 1) + 1], w.y, h[q]);
            }
        }
#pragma unroll
        for (int q = 0; q < 4; q++) {
            float lo, hi; unpack2(h[q], lo, hi);
            float t = fast_tanh(lo + hi);
            th[q] = pack2(t, t);
        }
        // layer 2 partial: y_i += tanh(h_j) * W2[j][i]  (16 independent yp chains)
#pragma unroll
        for (int q = 0; q < 4; q++) {
#pragma unroll
            for (int i = 0; i < 32; i += 4) {
                const ulonglong2 w = *reinterpret_cast<const ulonglong2*>(p2 + q * WROWSTR + i);
                yp[i >> 1]       = fma2(th[q], w.x, yp[i >> 1]);
                yp[(i >> 1) + 1] = fma2(th[q], w.y, yp[(i >> 1) + 1]);
            }
        }
        p1 += 4 * WROWSTR;
        p2 += 4 * WROWSTR;
    }
    // quad all-reduce (lanes s=0..3 of each element) + b2
#pragma unroll
    for (int p = 0; p < 16; p++) {
        float lo, hi; unpack2(yp[p], lo, hi);
        lo += __shfl_xor_sync(0xffffffffu, lo, 1);
        hi += __shfl_xor_sync(0xffffffffu, hi, 1);
        lo += __shfl_xor_sync(0xffffffffu, lo, 2);
        hi += __shfl_xor_sync(0xffffffffu, hi, 2);
        yp[p] = pack2(lo + sB2[2 * p], hi + sB2[2 * p + 1]);
    }
}

__global__ void __launch_bounds__(THREADS_PER_CTA)
ode_rk4_kernel(const float* __restrict__ x_in,
               const float* __restrict__ W1, const float* __restrict__ b1,
               const float* __restrict__ W2, const float* __restrict__ b2,
               const float* __restrict__ times, const int* __restrict__ ids32,
               float* __restrict__ out)
{
    __shared__ SmemLayout sm;
    const int tid = threadIdx.x;
    const int elem0 = blockIdx.x * ELEMS_PER_CTA;

    // ---- stage weights / biases / x / times into shared ----
#pragma unroll 1
    for (int idx = tid; idx < D_DIM * H_DIM; idx += THREADS_PER_CTA) {
        int i = idx >> 6, j = idx & 63;
        sm.w1[(j & 15) * WROWSTR + (j >> 4) * WSUBSTR + i] = W1[idx];
    }
#pragma unroll 1
    for (int idx = tid; idx < H_DIM * D_DIM; idx += THREADS_PER_CTA) {
        int j = idx >> 5, i = idx & 31;
        sm.w2[(j & 15) * WROWSTR + (j >> 4) * WSUBSTR + i] = W2[idx];
    }
    if (tid < H_DIM) sm.b1g[(tid & 15) * 4 + (tid >> 4)] = b1[tid];
    if (tid < D_DIM) sm.b2[tid] = b2[tid];
    if (tid < T_STEPS) sm.times[tid] = times[tid];
#pragma unroll 1
    for (int idx = tid; idx < ELEMS_PER_CTA * D_DIM; idx += THREADS_PER_CTA) {
        int e = idx >> 5, i = idx & 31;
        sm.x[e * XSTRIDE + i] = x_in[(elem0 + e) * D_DIM + i];
    }

    // ids dtype auto-detect: jax usually demotes int64->int32; if truly int64,
    // all odd 32-bit words (high halves, values < 32) are zero.
    bool wide = true;
#pragma unroll 1
    for (int k = 1; k < 64; k += 2) wide = wide && (ids32[k] == 0);

    __syncthreads();

    const int lane = tid & 31;
    const int e    = ((tid >> 5) << 3) + (lane >> 2);   // element slot 0..15 in CTA
    const int s    = lane & 3;                          // sub-thread 0..3 of element
    const int ge   = elem0 + e;
    const int id   = wide ? ids32[2 * ge] : ids32[ge];

    float* __restrict__ sx = sm.x + e * XSTRIDE;
    const float* w1b = sm.w1 + s * WSUBSTR;
    const float* w2b = sm.w2 + s * WSUBSTR;
    const float* b1b = sm.b1g + s;

    if (s == 0) out[ge] = sx[id];                       // t = 0 output

    uint64_t zp[16], yp[16], accp[16];
    const uint64_t two2 = pack2(2.0f, 2.0f);

#pragma unroll 1
    for (int t = 1; t < T_STEPS; t++) {
        const float hstep = (sm.times[t] - sm.times[t - 1]) * (1.0f / NSUB);
        const uint64_t h2  = pack2(hstep, hstep);
        const uint64_t hh2 = pack2(0.5f * hstep, 0.5f * hstep);
        const uint64_t h62 = pack2(hstep * (1.0f / 6.0f), hstep * (1.0f / 6.0f));

#pragma unroll 1
        for (int sub = 0; sub < NSUB; sub++) {
            // k1
#pragma unroll
            for (int p = 0; p < 16; p++)
                zp[p] = *reinterpret_cast<const uint64_t*>(sx + 2 * p);
            eval_field(zp, yp, w1b, w2b, b1b, sm.b2);
#pragma unroll
            for (int p = 0; p < 16; p++) {
                accp[p] = yp[p];
                zp[p]   = fma2(hh2, yp[p], zp[p]);      // x + 0.5h*k1 (zp held x)
            }
            // k2
            eval_field(zp, yp, w1b, w2b, b1b, sm.b2);
#pragma unroll
            for (int p = 0; p < 16; p++) {
                accp[p] = fma2(two2, yp[p], accp[p]);
                zp[p]   = fma2(hh2, yp[p], *reinterpret_cast<const uint64_t*>(sx + 2 * p));
            }
            // k3
            eval_field(zp, yp, w1b, w2b, b1b, sm.b2);
#pragma unroll
            for (int p = 0; p < 16; p++) {
                accp[p] = fma2(two2, yp[p], accp[p]);
                zp[p]   = fma2(h2, yp[p], *reinterpret_cast<const uint64_t*>(sx + 2 * p));
            }
            // k4
            eval_field(zp, yp, w1b, w2b, b1b, sm.b2);
#pragma unroll
            for (int p = 0; p < 16; p++) {
                accp[p] = add2(accp[p], yp[p]);
                zp[p]   = fma2(h62, accp[p], *reinterpret_cast<const uint64_t*>(sx + 2 * p));
            }
            __syncwarp();                                // old-x reads done before overwrite
            if (s == 0) {
#pragma unroll
                for (int p = 0; p < 16; p++)
                    *reinterpret_cast<uint64_t*>(sx + 2 * p) = zp[p];
            }
            __syncwarp();                                // new x visible to all lanes
        }
        if (s == 0) out[t * B_SZ + ge] = sx[id];
    }
}

extern "C" void kernel_launch(void* const* d_in, const int* in_sizes, int n_in,
                              void* d_out, int out_size) {
    (void)in_sizes; (void)n_in; (void)out_size;
    const float* x     = (const float*)d_in[0];
    const float* W1    = (const float*)d_in[1];
    const float* b1    = (const float*)d_in[2];
    const float* W2    = (const float*)d_in[3];
    const float* b2    = (const float*)d_in[4];
    const float* times = (const float*)d_in[5];
    const int*   ids   = (const int*)d_in[6];
    float* out = (float*)d_out;

    ode_rk4_kernel<<<B_SZ / ELEMS_PER_CTA, THREADS_PER_CTA>>>(
        x, W1, b1, W2, b2, times, ids, out);
}